// round 10
// baseline (speedup 1.0000x reference)
#include <cuda_runtime.h>
#include <cuda_bf16.h>
#include <math.h>
#include <stdint.h>

#define N 8192
#define D 32
#define NB 64
#define B 128
#define GAMMA 0.03125f
#define REG 1e-3f
#define GRID_CHOL 148
#define SSTR 10240u          // one split buffer: 128 rows x 80B pitch
#define SB_OFF (3u * SSTR)   // B splits start (within a stage)
#define STGO (6u * SSTR)     // stage stride = 61440
#define CHOL_DYN 122880      // 2 stages

// ---------------- device scratch ----------------
__device__ float g_A[(size_t)N * N];
__device__ float g_invL[(size_t)NB * B * B];
__device__ __align__(16) __nv_bfloat16 g_L0[(size_t)N * N];
__device__ __align__(16) __nv_bfloat16 g_L1[(size_t)N * N];
__device__ __align__(16) __nv_bfloat16 g_L2[(size_t)N * N];
__device__ __align__(16) __nv_bfloat16 g_W0[(size_t)NB * B * B];
__device__ __align__(16) __nv_bfloat16 g_W1[(size_t)NB * B * B];
__device__ __align__(16) __nv_bfloat16 g_W2[(size_t)NB * B * B];
__device__ float g_xx[N];
__device__ float g_r[N];
__device__ float g_zsol[N];
__device__ float g_alpha[N];
__device__ int   g_tflag[NB * NB];
__device__ int   g_cnt[NB + 1];
__device__ int   g_done[NB + 1];
__device__ int   g_ff[NB];
__device__ int   g_fb[NB];

// ---------------- helpers ----------------
__device__ __forceinline__ uint32_t s2u(const void* p) {
    uint32_t a;
    asm("{ .reg .u64 t; cvta.to.shared.u64 t, %1; cvt.u32.u64 %0, t; }" : "=r"(a) : "l"(p));
    return a;
}
__device__ __forceinline__ void ldsm_x4(uint32_t* d, uint32_t addr) {
    asm volatile("ldmatrix.sync.aligned.m8n8.x4.shared.b16 {%0,%1,%2,%3}, [%4];"
        : "=r"(d[0]), "=r"(d[1]), "=r"(d[2]), "=r"(d[3]) : "r"(addr));
}
__device__ __forceinline__ void ldsm_x2(uint32_t* d, uint32_t addr) {
    asm volatile("ldmatrix.sync.aligned.m8n8.x2.shared.b16 {%0,%1}, [%2];"
        : "=r"(d[0]), "=r"(d[1]) : "r"(addr));
}
__device__ __forceinline__ void mma16816(float* c, const uint32_t* a, const uint32_t* b) {
    asm volatile("mma.sync.aligned.m16n8k16.row.col.f32.bf16.bf16.f32 "
        "{%0,%1,%2,%3}, {%4,%5,%6,%7}, {%8,%9}, {%0,%1,%2,%3};"
        : "+f"(c[0]), "+f"(c[1]), "+f"(c[2]), "+f"(c[3])
        : "r"(a[0]), "r"(a[1]), "r"(a[2]), "r"(a[3]), "r"(b[0]), "r"(b[1]));
}
__device__ __forceinline__ void cpasync16(uint32_t saddr, const void* g) {
    asm volatile("cp.async.cg.shared.global [%0], [%1], 16;" :: "r"(saddr), "l"(g));
}
__device__ __forceinline__ void split3(float x, __nv_bfloat16& h0, __nv_bfloat16& h1, __nv_bfloat16& h2) {
    h0 = __float2bfloat16(x);
    float r1 = x - __bfloat162float(h0);
    h1 = __float2bfloat16(r1);
    h2 = __float2bfloat16(r1 - __bfloat162float(h1));
}
__device__ __forceinline__ void tri_decode_row(int p, int& ti, int& tj) {
    float pf = sqrtf(8.f * (float)p + 1.f);
    int i = (int)((pf - 1.f) * 0.5f);
    while ((i + 1) * (i + 2) / 2 <= p) i++;
    while (i * (i + 1) / 2 > p) i--;
    ti = i; tj = p - i * (i + 1) / 2;
}

__global__ void noop_kernel() {}

// ---------------- prep ----------------
__global__ void prep_kernel(const float* __restrict__ Xtr, const float* __restrict__ y) {
    int i = blockIdx.x * 256 + threadIdx.x;
    float s = 0.f;
#pragma unroll
    for (int dg = 0; dg < 8; dg++) {
        float4 v = *(const float4*)(Xtr + (size_t)i * D + dg * 4);
        s += v.x * v.x + v.y * v.y + v.z * v.z + v.w * v.w;
    }
    g_xx[i] = s;
    g_r[i] = y[i];
    if (i < NB * NB) g_tflag[i] = 0;
    if (i <= NB) { g_cnt[i] = 0; g_done[i] = 0; }
    if (i < NB) { g_ff[i] = 0; g_fb[i] = 0; }
}

// ---------------- build gram (lower triangle of 128-blocks) ----------------
__global__ void __launch_bounds__(256, 2) build_kernel(const float* __restrict__ Xtr) {
    __shared__ float sXi[32 * 132];
    __shared__ float sXj[32 * 132];
    __shared__ float sxxi[128], sxxj[128];
    int tid = threadIdx.x;
    int bi, bj;
    tri_decode_row(blockIdx.x, bi, bj);

#pragma unroll
    for (int i = 0; i < 4; i++) {
        int f = tid + i * 256;
        int r = f >> 3;
        int dg = (f & 7) << 2;
        float4 v = *(const float4*)(Xtr + (size_t)(bi * B + r) * D + dg);
        sXi[(dg + 0) * 132 + r] = v.x; sXi[(dg + 1) * 132 + r] = v.y;
        sXi[(dg + 2) * 132 + r] = v.z; sXi[(dg + 3) * 132 + r] = v.w;
        float4 w = *(const float4*)(Xtr + (size_t)(bj * B + r) * D + dg);
        sXj[(dg + 0) * 132 + r] = w.x; sXj[(dg + 1) * 132 + r] = w.y;
        sXj[(dg + 2) * 132 + r] = w.z; sXj[(dg + 3) * 132 + r] = w.w;
    }
    if (tid < 128) { sxxi[tid] = g_xx[bi * B + tid]; sxxj[tid] = g_xx[bj * B + tid]; }
    __syncthreads();

    int tm = tid >> 4, tn = tid & 15;
    float acc[8][8];
#pragma unroll
    for (int i = 0; i < 8; i++)
#pragma unroll
        for (int j = 0; j < 8; j++) acc[i][j] = 0.f;

#pragma unroll
    for (int d = 0; d < 32; d++) {
        float a[8], b[8];
        *(float4*)(a)     = *(const float4*)(&sXi[d * 132 + tm * 8]);
        *(float4*)(a + 4) = *(const float4*)(&sXi[d * 132 + tm * 8 + 4]);
        *(float4*)(b)     = *(const float4*)(&sXj[d * 132 + tn * 8]);
        *(float4*)(b + 4) = *(const float4*)(&sXj[d * 132 + tn * 8 + 4]);
#pragma unroll
        for (int i = 0; i < 8; i++)
#pragma unroll
            for (int j = 0; j < 8; j++) acc[i][j] += a[i] * b[j];
    }

#pragma unroll
    for (int i = 0; i < 8; i++) {
        int li = tm * 8 + i;
        int gi = bi * B + li;
        float v[8];
#pragma unroll
        for (int j = 0; j < 8; j++) {
            int lj = tn * 8 + j;
            int gj = bj * B + lj;
            float sq = sxxi[li] + sxxj[lj] - 2.f * acc[i][j];
            sq = fmaxf(sq, 0.f);
            float val = __expf(-GAMMA * sq);
            if (gi == gj) val += REG;
            v[j] = val;
        }
        float* cp = g_A + (size_t)gi * N + bj * B + tn * 8;
        *(float4*)(cp)     = make_float4(v[0], v[1], v[2], v[3]);
        *(float4*)(cp + 4) = make_float4(v[4], v[5], v[6], v[7]);
    }
}

// ---------------- async stage: one operand (3 splits) of a 32-col chunk ----------------
__device__ __forceinline__ void stage_async(const __nv_bfloat16* p0, const __nv_bfloat16* p1,
                                            const __nv_bfloat16* p2, int ld, int kk,
                                            uint32_t dst, int tid) {
#pragma unroll
    for (int i = 0; i < 6; i++) {
        int f = tid + (i << 8);
        int s = f >> 9;
        int rem = f & 511;
        int r = rem >> 2;
        int seg = rem & 3;
        const __nv_bfloat16* p = (s == 0) ? p0 : ((s == 1) ? p1 : p2);
        cpasync16(dst + (uint32_t)s * SSTR + r * 80 + seg * 16,
                  p + (size_t)r * ld + kk + seg * 8);
    }
}

// ---------------- compute one 32-col chunk into acc (reordered: low reg pressure) ----------------
__device__ __forceinline__ void compute_chunk(uint32_t abase, uint32_t bbase,
                                              int lane, int wm, int wn,
                                              float acc[2][8][4]) {
#pragma unroll
    for (int kt = 0; kt < 2; kt++) {
#pragma unroll
        for (int sb = 0; sb < 3; sb++) {
            uint32_t bfr[8][2];
#pragma unroll
            for (int nt = 0; nt < 8; nt++) {
                int n = wn * 64 + nt * 8 + (lane & 7);
                int col = kt * 16 + ((lane >> 3) & 1) * 8;
                ldsm_x2(bfr[nt], bbase + (uint32_t)sb * SSTR + n * 80 + col * 2);
            }
#pragma unroll
            for (int sa = 0; sa < 3; sa++) {
                if (sa + sb > 2) continue;
                uint32_t af[2][4];
#pragma unroll
                for (int mt = 0; mt < 2; mt++) {
                    int rrow = wm * 32 + mt * 16 + (lane & 15);
                    int col = kt * 16 + (lane >> 4) * 8;
                    ldsm_x4(af[mt], abase + (uint32_t)sa * SSTR + rrow * 80 + col * 2);
                }
#pragma unroll
                for (int mt = 0; mt < 2; mt++)
#pragma unroll
                    for (int nt = 0; nt < 8; nt++)
                        mma16816(acc[mt][nt], af[mt], bfr[nt]);
            }
        }
    }
}

// ---------------- HMMA split-bf16 tile GEMM: C (op)= A(128x128) * B(128x128)^T ----------------
__device__ void mma_tile(const float* Afp,
                         const __nv_bfloat16* Ab0, const __nv_bfloat16* Ab1,
                         const __nv_bfloat16* Ab2, int lda,
                         const __nv_bfloat16* Bb0, const __nv_bfloat16* Bb1,
                         const __nv_bfloat16* Bb2, int ldb,
                         float* C,
                         __nv_bfloat16* O0, __nv_bfloat16* O1, __nv_bfloat16* O2,
                         bool sub, char* dsm, uint32_t sbase) {
    int tid = threadIdx.x;
    int lane = tid & 31, warp = tid >> 5;
    int wm = warp & 3, wn = warp >> 2;

    float acc[2][8][4];
#pragma unroll
    for (int mt = 0; mt < 2; mt++)
#pragma unroll
        for (int nt = 0; nt < 8; nt++)
#pragma unroll
            for (int e = 0; e < 4; e++) acc[mt][nt][e] = 0.f;

    if (Afp) {
        // ---- trsm path: single-buffered, A split synchronously ----
        for (int ck = 0; ck < 4; ck++) {
            int kk = ck * 32;
            stage_async(Bb0, Bb1, Bb2, ldb, kk, sbase + SB_OFF, tid);
            asm volatile("cp.async.commit_group;");
#pragma unroll
            for (int i = 0; i < 16; i++) {
                int f = tid + (i << 8);
                int r = f >> 5, c = f & 31;
                float v = Afp[(size_t)r * N + kk + c];
                __nv_bfloat16 h0, h1, h2;
                split3(v, h0, h1, h2);
                int so = r * 80 + c * 2;
                *(__nv_bfloat16*)(dsm + so) = h0;
                *(__nv_bfloat16*)(dsm + SSTR + so) = h1;
                *(__nv_bfloat16*)(dsm + 2 * SSTR + so) = h2;
            }
            asm volatile("cp.async.wait_group 0;" ::: "memory");
            __syncthreads();
            compute_chunk(sbase, sbase + SB_OFF, lane, wm, wn, acc);
            __syncthreads();
        }
    } else {
        // ---- syrk path: 2-stage cp.async pipeline ----
        stage_async(Ab0, Ab1, Ab2, lda, 0, sbase, tid);
        stage_async(Bb0, Bb1, Bb2, ldb, 0, sbase + SB_OFF, tid);
        asm volatile("cp.async.commit_group;");
#pragma unroll
        for (int ck = 0; ck < 4; ck++) {
            uint32_t cur = sbase + (uint32_t)(ck & 1) * STGO;
            if (ck < 3) {
                uint32_t nxt = sbase + (uint32_t)((ck + 1) & 1) * STGO;
                int kk = (ck + 1) * 32;
                stage_async(Ab0, Ab1, Ab2, lda, kk, nxt, tid);
                stage_async(Bb0, Bb1, Bb2, ldb, kk, nxt + SB_OFF, tid);
                asm volatile("cp.async.commit_group;");
                asm volatile("cp.async.wait_group 1;" ::: "memory");
            } else {
                asm volatile("cp.async.wait_group 0;" ::: "memory");
            }
            __syncthreads();
            compute_chunk(cur, cur + SB_OFF, lane, wm, wn, acc);
            __syncthreads();
        }
    }

    // epilogue via smem staging (two 64-row halves), coalesced fp32 update
    float* sE = (float*)dsm;
    for (int half = 0; half < 2; half++) {
        if ((wm >> 1) == half) {
#pragma unroll
            for (int mt = 0; mt < 2; mt++)
#pragma unroll
                for (int nt = 0; nt < 8; nt++) {
                    int rb = (wm & 1) * 32 + mt * 16 + (lane >> 2);
                    int cb = wn * 64 + nt * 8 + (lane & 3) * 2;
                    sE[rb * 132 + cb]           = acc[mt][nt][0];
                    sE[rb * 132 + cb + 1]       = acc[mt][nt][1];
                    sE[(rb + 8) * 132 + cb]     = acc[mt][nt][2];
                    sE[(rb + 8) * 132 + cb + 1] = acc[mt][nt][3];
                }
        }
        __syncthreads();
#pragma unroll
        for (int i = 0; i < 8; i++) {
            int flat = i * 256 + tid;
            int rr = flat >> 5;
            int c4 = (flat & 31) * 4;
            int grow = half * 64 + rr;
            float* cp = C + (size_t)grow * N + c4;
            float4 s = *(float4*)(sE + rr * 132 + c4);
            if (sub) {
                float4 c0 = *(float4*)cp;
                c0.x -= s.x; c0.y -= s.y; c0.z -= s.z; c0.w -= s.w;
                *(float4*)cp = c0;
            } else {
                *(float4*)cp = s;
                size_t ob = (size_t)grow * N + c4;
                __nv_bfloat16 a0, a1, a2, b0, b1, b2, c0_, c1_, c2_, d0, d1, d2;
                split3(s.x, a0, a1, a2); split3(s.y, b0, b1, b2);
                split3(s.z, c0_, c1_, c2_); split3(s.w, d0, d1, d2);
                *(__nv_bfloat162*)(O0 + ob)     = __halves2bfloat162(a0, b0);
                *(__nv_bfloat162*)(O0 + ob + 2) = __halves2bfloat162(c0_, d0);
                *(__nv_bfloat162*)(O1 + ob)     = __halves2bfloat162(a1, b1);
                *(__nv_bfloat162*)(O1 + ob + 2) = __halves2bfloat162(c1_, d1);
                *(__nv_bfloat162*)(O2 + ob)     = __halves2bfloat162(a2, b2);
                *(__nv_bfloat162*)(O2 + ob + 2) = __halves2bfloat162(c2_, d2);
            }
        }
        __syncthreads();
    }
}

// ---------------- potf: factor diag block kb, write invL + splits ----------------
__device__ void potf_block(int kb, float* sD, float* invd, float* rowbuf) {
    int tid = threadIdx.x;
    size_t base = (size_t)(kb * B) * N + (size_t)kb * B;

    for (int idx = tid; idx < B * B; idx += 256) {
        int r = idx >> 7, c = idx & 127;
        sD[r * 129 + c] = g_A[base + (size_t)r * N + c];
    }
    __syncthreads();

    int tr = tid & 31, tj2 = tid >> 5;
    for (int c = 0; c < B - 1; c++) {
        float ipiv = __fdividef(1.f, sD[c * 129 + c]);
        for (int r = c + 1 + tr; r < B; r += 32) {
            float a = sD[r * 129 + c] * ipiv;
            for (int jj = c + 1 + tj2; jj <= r; jj += 8)
                sD[r * 129 + jj] -= a * sD[jj * 129 + c];
        }
        __syncthreads();
    }
    for (int c = tid; c < B; c += 256) invd[c] = rsqrtf(sD[c * 129 + c]);
    __syncthreads();
    for (int idx = tid; idx < B * B; idx += 256) {
        int r = idx >> 7, c = idx & 127;
        if (c < r) sD[r * 129 + c] *= invd[c];
        else if (c == r) sD[r * 129 + c] = invd[c];
    }
    __syncthreads();

    for (int r = 1; r < B; r++) {
        for (int c = tid; c < r; c += 256) rowbuf[c] = sD[r * 129 + c];
        __syncthreads();
        if (tid < r) {
            int c = tid;
            float a0 = 0.f, a1 = 0.f, a2 = 0.f, a3 = 0.f;
            int jj = c;
            for (; jj + 3 < r; jj += 4) {
                a0 += rowbuf[jj]     * sD[jj * 129 + c];
                a1 += rowbuf[jj + 1] * sD[(jj + 1) * 129 + c];
                a2 += rowbuf[jj + 2] * sD[(jj + 2) * 129 + c];
                a3 += rowbuf[jj + 3] * sD[(jj + 3) * 129 + c];
            }
            for (; jj < r; jj++) a0 += rowbuf[jj] * sD[jj * 129 + c];
            sD[r * 129 + c] = -invd[r] * ((a0 + a1) + (a2 + a3));
        }
        __syncthreads();
    }
    size_t koff = (size_t)kb * B * B;
    for (int idx = tid; idx < B * B; idx += 256) {
        int r = idx >> 7, c = idx & 127;
        float w = (c <= r) ? sD[r * 129 + c] : 0.f;
        g_invL[koff + idx] = w;
        __nv_bfloat16 h0, h1, h2;
        split3(w, h0, h1, h2);
        g_W0[koff + idx] = h0;
        g_W1[koff + idx] = h1;
        g_W2[koff + idx] = h2;
    }
    __syncthreads();
}

// ---------------- persistent right-looking cholesky (HMMA GEMMs) ----------------
__device__ __forceinline__ void barrier_phase(int pid) {
    __syncthreads();
    if (threadIdx.x == 0) {
        __threadfence();
        atomicAdd(&g_done[pid], 1);
        while (((volatile int*)g_done)[pid] < GRID_CHOL) __nanosleep(64);
        __threadfence();
    }
    __syncthreads();
}

__global__ void __launch_bounds__(256, 1) chol_kernel() {
    extern __shared__ char dsm[];
    uint32_t sbase = s2u(dsm);
    __shared__ float invd[128];
    __shared__ float rowbuf[128];
    __shared__ int s_t;

    int tid = threadIdx.x;

    if (blockIdx.x == 0) potf_block(0, (float*)dsm, invd, rowbuf);
    barrier_phase(NB);

    for (int k = 0; k < NB - 1; k++) {
        int nb = NB - 1 - k;
        int ntask = nb + nb * (nb + 1) / 2;
        volatile int* tf = (volatile int*)(g_tflag + k * NB);
        size_t koff = (size_t)k * B * B;

        while (true) {
            if (tid == 0) s_t = atomicAdd(&g_cnt[k], 1);
            __syncthreads();
            int t = s_t;
            if (t >= ntask) break;

            if (t < nb) {
                int i = k + 1 + t;
                size_t poff = (size_t)(i * B) * N + (size_t)k * B;
                mma_tile(g_A + poff, 0, 0, 0, 0,
                         g_W0 + koff, g_W1 + koff, g_W2 + koff, B,
                         g_A + poff,
                         g_L0 + poff, g_L1 + poff, g_L2 + poff,
                         false, dsm, sbase);
                __threadfence();
                __syncthreads();
                if (tid == 0) atomicExch(&g_tflag[k * NB + i], 1);
            } else {
                int p, q;
                tri_decode_row(t - nb, p, q);
                int a = k + 1 + p, b = k + 1 + q;
                if (tid == 0) {
                    while (tf[a] == 0) __nanosleep(32);
                    while (tf[b] == 0) __nanosleep(32);
                }
                __syncthreads();
                __threadfence();
                size_t aoff = (size_t)(a * B) * N + (size_t)k * B;
                size_t boff = (size_t)(b * B) * N + (size_t)k * B;
                mma_tile(0, g_L0 + aoff, g_L1 + aoff, g_L2 + aoff, N,
                         g_L0 + boff, g_L1 + boff, g_L2 + boff, N,
                         g_A + (size_t)(a * B) * N + (size_t)b * B,
                         0, 0, 0, true, dsm, sbase);
                if (t == nb) {
                    __syncthreads();
                    potf_block(k + 1, (float*)dsm, invd, rowbuf);
                }
            }
            __syncthreads();
        }
        barrier_phase(k);
    }
}

// ---------------- spin-chained forward solve (512 thr) ----------------
__global__ void __launch_bounds__(512, 1) fwd_solve() {
    int k = blockIdx.x;
    int tid = threadIdx.x;
    int t = tid & 127, q = tid >> 7;
    __shared__ float svec[128];
    __shared__ float red[512];
    float acc = (q == 0) ? g_r[k * B + t] : 0.f;
    for (int j = 0; j < k; j++) {
        if (tid == 0) { while (((volatile int*)g_ff)[j] == 0) __nanosleep(32); }
        __syncthreads();
        __threadfence();
        if (tid < 128) svec[tid] = g_zsol[j * B + tid];
        __syncthreads();
        const float* Lr = g_A + (size_t)(k * B + t) * N + (size_t)j * B + q * 32;
        float a0 = 0.f, a1 = 0.f;
#pragma unroll
        for (int c = 0; c < 32; c += 8) {
            float4 l0 = *(const float4*)(Lr + c);
            float4 l1 = *(const float4*)(Lr + c + 4);
            int cc = q * 32 + c;
            a0 += l0.x * svec[cc] + l0.y * svec[cc + 1] + l0.z * svec[cc + 2] + l0.w * svec[cc + 3];
            a1 += l1.x * svec[cc + 4] + l1.y * svec[cc + 5] + l1.z * svec[cc + 6] + l1.w * svec[cc + 7];
        }
        acc -= a0 + a1;
        __syncthreads();
    }
    red[q * 128 + t] = acc;
    __syncthreads();
    if (tid < 128) svec[tid] = red[tid] + red[128 + tid] + red[256 + tid] + red[384 + tid];
    __syncthreads();
    const float* Wr = g_invL + (size_t)k * B * B + (size_t)t * B + q * 32;
    float z = 0.f;
#pragma unroll
    for (int c = 0; c < 32; c += 4) {
        float4 w = *(const float4*)(Wr + c);
        int cc = q * 32 + c;
        z += w.x * svec[cc] + w.y * svec[cc + 1] + w.z * svec[cc + 2] + w.w * svec[cc + 3];
    }
    red[q * 128 + t] = z;
    __syncthreads();
    if (tid < 128) g_zsol[k * B + tid] = red[tid] + red[128 + tid] + red[256 + tid] + red[384 + tid];
    __threadfence();
    __syncthreads();
    if (tid == 0) atomicExch(&g_ff[k], 1);
}

// ---------------- spin-chained backward solve (512 thr) ----------------
__global__ void __launch_bounds__(512, 1) bwd_solve() {
    int k = NB - 1 - blockIdx.x;
    int tid = threadIdx.x;
    int t = tid & 127, q = tid >> 7;
    __shared__ float svec[128];
    __shared__ float red[512];
    float acc = (q == 0) ? g_zsol[k * B + t] : 0.f;
    for (int j = k + 1; j < NB; j++) {
        if (tid == 0) { while (((volatile int*)g_fb)[j] == 0) __nanosleep(32); }
        __syncthreads();
        __threadfence();
        if (tid < 128) svec[tid] = g_alpha[j * B + tid];
        __syncthreads();
        const float* Lc = g_A + (size_t)(j * B + q * 32) * N + (size_t)k * B + t;
        float a0 = 0.f, a1 = 0.f, a2 = 0.f, a3 = 0.f;
#pragma unroll
        for (int r = 0; r < 32; r += 4) {
            int rr = q * 32 + r;
            a0 += Lc[(size_t)(r + 0) * N] * svec[rr + 0];
            a1 += Lc[(size_t)(r + 1) * N] * svec[rr + 1];
            a2 += Lc[(size_t)(r + 2) * N] * svec[rr + 2];
            a3 += Lc[(size_t)(r + 3) * N] * svec[rr + 3];
        }
        acc -= ((a0 + a1) + (a2 + a3));
        __syncthreads();
    }
    red[q * 128 + t] = acc;
    __syncthreads();
    if (tid < 128) svec[tid] = red[tid] + red[128 + tid] + red[256 + tid] + red[384 + tid];
    __syncthreads();
    const float* Wc = g_invL + (size_t)k * B * B + (size_t)(q * 32) * B + t;
    float al = 0.f;
#pragma unroll 8
    for (int r = 0; r < 32; r++) al += Wc[(size_t)r * B] * svec[q * 32 + r];
    red[q * 128 + t] = al;
    __syncthreads();
    if (tid < 128) g_alpha[k * B + tid] = red[tid] + red[128 + tid] + red[256 + tid] + red[384 + tid];
    __threadfence();
    __syncthreads();
    if (tid == 0) atomicExch(&g_fb[k], 1);
}

// ---------------- fused predict ----------------
__global__ void __launch_bounds__(256, 2) predict_kernel(const float* __restrict__ Xte,
                                                         const float* __restrict__ Xtr,
                                                         float* __restrict__ out) {
    __shared__ float sTr[32 * 132];
    __shared__ float sAl[128], sXX[128];
    __shared__ float sRed[256];
    int tid = threadIdx.x;
    int rl = tid >> 3, sl = tid & 7;
    int grow = blockIdx.x * 32 + rl;

    float xt[32];
#pragma unroll
    for (int dg = 0; dg < 8; dg++)
        *(float4*)(xt + dg * 4) = *(const float4*)(Xte + (size_t)grow * D + dg * 4);
    float xxt = 0.f;
#pragma unroll
    for (int d = 0; d < 32; d++) xxt += xt[d] * xt[d];

    float acc = 0.f;
    for (int ch = 0; ch < N / 128; ch++) {
        int pbase = ch * 128;
        __syncthreads();
#pragma unroll
        for (int i = 0; i < 4; i++) {
            int f = tid + i * 256;
            int p = f >> 3;
            int dg = (f & 7) << 2;
            float4 v = *(const float4*)(Xtr + (size_t)(pbase + p) * D + dg);
            sTr[(dg + 0) * 132 + p] = v.x; sTr[(dg + 1) * 132 + p] = v.y;
            sTr[(dg + 2) * 132 + p] = v.z; sTr[(dg + 3) * 132 + p] = v.w;
        }
        if (tid < 128) { sAl[tid] = g_alpha[pbase + tid]; sXX[tid] = g_xx[pbase + tid]; }
        __syncthreads();
#pragma unroll 4
        for (int i = 0; i < 16; i++) {
            int p = i * 8 + sl;
            float dot = 0.f;
#pragma unroll
            for (int d = 0; d < 32; d++) dot += xt[d] * sTr[d * 132 + p];
            float sq = fmaxf(xxt + sXX[p] - 2.f * dot, 0.f);
            acc += __expf(-GAMMA * sq) * sAl[p];
        }
    }
    sRed[rl * 8 + sl] = acc;
    __syncthreads();
    if (tid < 32) {
        float s = 0.f;
#pragma unroll
        for (int j = 0; j < 8; j++) s += sRed[tid * 8 + j];
        out[blockIdx.x * 32 + tid] = s;
    }
}

// ---------------- launcher ----------------
extern "C" void kernel_launch(void* const* d_in, const int* in_sizes, int n_in,
                              void* d_out, int out_size) {
    const float* Xtr = (const float*)d_in[0];
    const float* y   = (const float*)d_in[1];
    const float* Xte = (const float*)d_in[2];
    float* out = (float*)d_out;

    cudaFuncSetAttribute(chol_kernel, cudaFuncAttributeMaxDynamicSharedMemorySize, CHOL_DYN);

    prep_kernel<<<N / 256, 256>>>(Xtr, y);
    build_kernel<<<NB * (NB + 1) / 2, 256>>>(Xtr);
    noop_kernel<<<1, 1>>>();
    chol_kernel<<<GRID_CHOL, 256, CHOL_DYN>>>();   // 4th launch -> ncu captures this
    fwd_solve<<<NB, 512>>>();
    bwd_solve<<<NB, 512>>>();
    predict_kernel<<<N / 32, 256>>>(Xte, Xtr, out);
}

// round 11
// speedup vs baseline: 1.0932x; 1.0932x over previous
#include <cuda_runtime.h>
#include <cuda_bf16.h>
#include <math.h>
#include <stdint.h>

#define N 8192
#define D 32
#define NB 64
#define B 128
#define GAMMA 0.03125f
#define REG 1e-3f
#define GRID_CHOL 148
#define NTHR 512
#define SSTR 10240u          // one split buffer: 128 rows x 80B pitch
#define SB_OFF (3u * SSTR)   // B splits start
#define CHOL_DYN 66048       // potf staging 128x129 fp32 (>= 6*SSTR stage area)

// ---------------- device scratch ----------------
__device__ float g_A[(size_t)N * N];
__device__ float g_invL[(size_t)NB * B * B];
__device__ __align__(16) __nv_bfloat16 g_L0[(size_t)N * N];
__device__ __align__(16) __nv_bfloat16 g_L1[(size_t)N * N];
__device__ __align__(16) __nv_bfloat16 g_L2[(size_t)N * N];
__device__ __align__(16) __nv_bfloat16 g_W0[(size_t)NB * B * B];
__device__ __align__(16) __nv_bfloat16 g_W1[(size_t)NB * B * B];
__device__ __align__(16) __nv_bfloat16 g_W2[(size_t)NB * B * B];
__device__ float g_xx[N];
__device__ float g_r[N];
__device__ float g_zsol[N];
__device__ float g_alpha[N];
__device__ int   g_tflag[NB * NB];
__device__ int   g_cnt[NB + 1];
__device__ int   g_done[NB + 1];
__device__ int   g_ff[NB];
__device__ int   g_fb[NB];

// ---------------- helpers ----------------
__device__ __forceinline__ uint32_t s2u(const void* p) {
    uint32_t a;
    asm("{ .reg .u64 t; cvta.to.shared.u64 t, %1; cvt.u32.u64 %0, t; }" : "=r"(a) : "l"(p));
    return a;
}
__device__ __forceinline__ void ldsm_x4(uint32_t* d, uint32_t addr) {
    asm volatile("ldmatrix.sync.aligned.m8n8.x4.shared.b16 {%0,%1,%2,%3}, [%4];"
        : "=r"(d[0]), "=r"(d[1]), "=r"(d[2]), "=r"(d[3]) : "r"(addr));
}
__device__ __forceinline__ void ldsm_x2(uint32_t* d, uint32_t addr) {
    asm volatile("ldmatrix.sync.aligned.m8n8.x2.shared.b16 {%0,%1}, [%2];"
        : "=r"(d[0]), "=r"(d[1]) : "r"(addr));
}
__device__ __forceinline__ void mma16816(float* c, const uint32_t* a, const uint32_t* b) {
    asm volatile("mma.sync.aligned.m16n8k16.row.col.f32.bf16.bf16.f32 "
        "{%0,%1,%2,%3}, {%4,%5,%6,%7}, {%8,%9}, {%0,%1,%2,%3};"
        : "+f"(c[0]), "+f"(c[1]), "+f"(c[2]), "+f"(c[3])
        : "r"(a[0]), "r"(a[1]), "r"(a[2]), "r"(a[3]), "r"(b[0]), "r"(b[1]));
}
__device__ __forceinline__ void cpasync16(uint32_t saddr, const void* g) {
    asm volatile("cp.async.cg.shared.global [%0], [%1], 16;" :: "r"(saddr), "l"(g));
}
__device__ __forceinline__ void split3(float x, __nv_bfloat16& h0, __nv_bfloat16& h1, __nv_bfloat16& h2) {
    h0 = __float2bfloat16(x);
    float r1 = x - __bfloat162float(h0);
    h1 = __float2bfloat16(r1);
    h2 = __float2bfloat16(r1 - __bfloat162float(h1));
}
__device__ __forceinline__ void tri_decode_row(int p, int& ti, int& tj) {
    float pf = sqrtf(8.f * (float)p + 1.f);
    int i = (int)((pf - 1.f) * 0.5f);
    while ((i + 1) * (i + 2) / 2 <= p) i++;
    while (i * (i + 1) / 2 > p) i--;
    ti = i; tj = p - i * (i + 1) / 2;
}

__global__ void noop_kernel() {}

// ---------------- prep ----------------
__global__ void prep_kernel(const float* __restrict__ Xtr, const float* __restrict__ y) {
    int i = blockIdx.x * 256 + threadIdx.x;
    float s = 0.f;
#pragma unroll
    for (int dg = 0; dg < 8; dg++) {
        float4 v = *(const float4*)(Xtr + (size_t)i * D + dg * 4);
        s += v.x * v.x + v.y * v.y + v.z * v.z + v.w * v.w;
    }
    g_xx[i] = s;
    g_r[i] = y[i];
    if (i < NB * NB) g_tflag[i] = 0;
    if (i <= NB) { g_cnt[i] = 0; g_done[i] = 0; }
    if (i < NB) { g_ff[i] = 0; g_fb[i] = 0; }
}

// ---------------- build gram (lower triangle of 128-blocks) ----------------
__global__ void __launch_bounds__(256, 2) build_kernel(const float* __restrict__ Xtr) {
    __shared__ float sXi[32 * 132];
    __shared__ float sXj[32 * 132];
    __shared__ float sxxi[128], sxxj[128];
    int tid = threadIdx.x;
    int bi, bj;
    tri_decode_row(blockIdx.x, bi, bj);

#pragma unroll
    for (int i = 0; i < 4; i++) {
        int f = tid + i * 256;
        int r = f >> 3;
        int dg = (f & 7) << 2;
        float4 v = *(const float4*)(Xtr + (size_t)(bi * B + r) * D + dg);
        sXi[(dg + 0) * 132 + r] = v.x; sXi[(dg + 1) * 132 + r] = v.y;
        sXi[(dg + 2) * 132 + r] = v.z; sXi[(dg + 3) * 132 + r] = v.w;
        float4 w = *(const float4*)(Xtr + (size_t)(bj * B + r) * D + dg);
        sXj[(dg + 0) * 132 + r] = w.x; sXj[(dg + 1) * 132 + r] = w.y;
        sXj[(dg + 2) * 132 + r] = w.z; sXj[(dg + 3) * 132 + r] = w.w;
    }
    if (tid < 128) { sxxi[tid] = g_xx[bi * B + tid]; sxxj[tid] = g_xx[bj * B + tid]; }
    __syncthreads();

    int tm = tid >> 4, tn = tid & 15;
    float acc[8][8];
#pragma unroll
    for (int i = 0; i < 8; i++)
#pragma unroll
        for (int j = 0; j < 8; j++) acc[i][j] = 0.f;

#pragma unroll
    for (int d = 0; d < 32; d++) {
        float a[8], b[8];
        *(float4*)(a)     = *(const float4*)(&sXi[d * 132 + tm * 8]);
        *(float4*)(a + 4) = *(const float4*)(&sXi[d * 132 + tm * 8 + 4]);
        *(float4*)(b)     = *(const float4*)(&sXj[d * 132 + tn * 8]);
        *(float4*)(b + 4) = *(const float4*)(&sXj[d * 132 + tn * 8 + 4]);
#pragma unroll
        for (int i = 0; i < 8; i++)
#pragma unroll
            for (int j = 0; j < 8; j++) acc[i][j] += a[i] * b[j];
    }

#pragma unroll
    for (int i = 0; i < 8; i++) {
        int li = tm * 8 + i;
        int gi = bi * B + li;
        float v[8];
#pragma unroll
        for (int j = 0; j < 8; j++) {
            int lj = tn * 8 + j;
            int gj = bj * B + lj;
            float sq = sxxi[li] + sxxj[lj] - 2.f * acc[i][j];
            sq = fmaxf(sq, 0.f);
            float val = __expf(-GAMMA * sq);
            if (gi == gj) val += REG;
            v[j] = val;
        }
        float* cp = g_A + (size_t)gi * N + bj * B + tn * 8;
        *(float4*)(cp)     = make_float4(v[0], v[1], v[2], v[3]);
        *(float4*)(cp + 4) = make_float4(v[4], v[5], v[6], v[7]);
    }
}

// ---------------- async stage: one operand (3 splits) of a 32-col chunk (512 thr) ----------------
__device__ __forceinline__ void stage_async(const __nv_bfloat16* p0, const __nv_bfloat16* p1,
                                            const __nv_bfloat16* p2, int ld, int kk,
                                            uint32_t dst, int tid) {
#pragma unroll
    for (int i = 0; i < 3; i++) {
        int f = tid + (i << 9);
        int s = f >> 9;
        int rem = f & 511;
        int r = rem >> 2;
        int seg = rem & 3;
        const __nv_bfloat16* p = (s == 0) ? p0 : ((s == 1) ? p1 : p2);
        cpasync16(dst + (uint32_t)s * SSTR + r * 80 + seg * 16,
                  p + (size_t)r * ld + kk + seg * 8);
    }
}

// ---------------- compute one 32-col chunk into acc (warp tile 32x32) ----------------
__device__ __forceinline__ void compute_chunk(uint32_t abase, uint32_t bbase,
                                              int lane, int wm, int wn,
                                              float acc[2][4][4]) {
#pragma unroll
    for (int kt = 0; kt < 2; kt++) {
#pragma unroll
        for (int sb = 0; sb < 3; sb++) {
            uint32_t bfr[4][2];
#pragma unroll
            for (int nt = 0; nt < 4; nt++) {
                int n = wn * 32 + nt * 8 + (lane & 7);
                int col = kt * 16 + ((lane >> 3) & 1) * 8;
                ldsm_x2(bfr[nt], bbase + (uint32_t)sb * SSTR + n * 80 + col * 2);
            }
#pragma unroll
            for (int sa = 0; sa < 3; sa++) {
                if (sa + sb > 2) continue;
                uint32_t af[2][4];
#pragma unroll
                for (int mt = 0; mt < 2; mt++) {
                    int rrow = wm * 32 + mt * 16 + (lane & 15);
                    int col = kt * 16 + (lane >> 4) * 8;
                    ldsm_x4(af[mt], abase + (uint32_t)sa * SSTR + rrow * 80 + col * 2);
                }
#pragma unroll
                for (int mt = 0; mt < 2; mt++)
#pragma unroll
                    for (int nt = 0; nt < 4; nt++)
                        mma16816(acc[mt][nt], af[mt], bfr[nt]);
            }
        }
    }
}

// ---------------- HMMA split-bf16 tile GEMM: C (op)= A(128x128) * B(128x128)^T ----------------
__device__ void mma_tile(const float* Afp,
                         const __nv_bfloat16* Ab0, const __nv_bfloat16* Ab1,
                         const __nv_bfloat16* Ab2, int lda,
                         const __nv_bfloat16* Bb0, const __nv_bfloat16* Bb1,
                         const __nv_bfloat16* Bb2, int ldb,
                         float* C,
                         __nv_bfloat16* O0, __nv_bfloat16* O1, __nv_bfloat16* O2,
                         bool sub, char* dsm, uint32_t sbase) {
    int tid = threadIdx.x;
    int lane = tid & 31, warp = tid >> 5;
    int wm = warp & 3, wn = warp >> 2;

    float acc[2][4][4];
#pragma unroll
    for (int mt = 0; mt < 2; mt++)
#pragma unroll
        for (int nt = 0; nt < 4; nt++)
#pragma unroll
            for (int e = 0; e < 4; e++) acc[mt][nt][e] = 0.f;

    for (int ck = 0; ck < 4; ck++) {
        int kk = ck * 32;
        stage_async(Bb0, Bb1, Bb2, ldb, kk, sbase + SB_OFF, tid);
        if (Afp) {
            asm volatile("cp.async.commit_group;");
            // sync load + split fp32 A chunk (512 thr: 8 elems each)
#pragma unroll
            for (int i = 0; i < 8; i++) {
                int f = tid + (i << 9);
                int r = f >> 5, c = f & 31;
                float v = Afp[(size_t)r * N + kk + c];
                __nv_bfloat16 h0, h1, h2;
                split3(v, h0, h1, h2);
                int so = r * 80 + c * 2;
                *(__nv_bfloat16*)(dsm + so) = h0;
                *(__nv_bfloat16*)(dsm + SSTR + so) = h1;
                *(__nv_bfloat16*)(dsm + 2 * SSTR + so) = h2;
            }
        } else {
            stage_async(Ab0, Ab1, Ab2, lda, kk, sbase, tid);
            asm volatile("cp.async.commit_group;");
        }
        asm volatile("cp.async.wait_group 0;" ::: "memory");
        __syncthreads();
        compute_chunk(sbase, sbase + SB_OFF, lane, wm, wn, acc);
        __syncthreads();
    }

    // epilogue via smem staging (two 64-row halves), coalesced fp32 update
    float* sE = (float*)dsm;
    for (int half = 0; half < 2; half++) {
        if ((wm >> 1) == half) {
#pragma unroll
            for (int mt = 0; mt < 2; mt++)
#pragma unroll
                for (int nt = 0; nt < 4; nt++) {
                    int rb = (wm & 1) * 32 + mt * 16 + (lane >> 2);
                    int cb = wn * 32 + nt * 8 + (lane & 3) * 2;
                    sE[rb * 132 + cb]           = acc[mt][nt][0];
                    sE[rb * 132 + cb + 1]       = acc[mt][nt][1];
                    sE[(rb + 8) * 132 + cb]     = acc[mt][nt][2];
                    sE[(rb + 8) * 132 + cb + 1] = acc[mt][nt][3];
                }
        }
        __syncthreads();
#pragma unroll
        for (int i = 0; i < 4; i++) {
            int flat = i * NTHR + tid;      // 0..2047 float4 units
            int rr = flat >> 5;
            int c4 = (flat & 31) * 4;
            int grow = half * 64 + rr;
            float* cp = C + (size_t)grow * N + c4;
            float4 s = *(float4*)(sE + rr * 132 + c4);
            if (sub) {
                float4 c0 = *(float4*)cp;
                c0.x -= s.x; c0.y -= s.y; c0.z -= s.z; c0.w -= s.w;
                *(float4*)cp = c0;
            } else {
                *(float4*)cp = s;
                size_t ob = (size_t)grow * N + c4;
                __nv_bfloat16 a0, a1, a2, b0, b1, b2, c0_, c1_, c2_, d0, d1, d2;
                split3(s.x, a0, a1, a2); split3(s.y, b0, b1, b2);
                split3(s.z, c0_, c1_, c2_); split3(s.w, d0, d1, d2);
                *(__nv_bfloat162*)(O0 + ob)     = __halves2bfloat162(a0, b0);
                *(__nv_bfloat162*)(O0 + ob + 2) = __halves2bfloat162(c0_, d0);
                *(__nv_bfloat162*)(O1 + ob)     = __halves2bfloat162(a1, b1);
                *(__nv_bfloat162*)(O1 + ob + 2) = __halves2bfloat162(c1_, d1);
                *(__nv_bfloat162*)(O2 + ob)     = __halves2bfloat162(a2, b2);
                *(__nv_bfloat162*)(O2 + ob + 2) = __halves2bfloat162(c2_, d2);
            }
        }
        __syncthreads();
    }
}

// ---------------- potf: factor diag block kb, write invL + splits (512 thr) ----------------
__device__ void potf_block(int kb, float* sD, float* invd, float* rowbuf) {
    int tid = threadIdx.x;
    size_t base = (size_t)(kb * B) * N + (size_t)kb * B;

    for (int idx = tid; idx < B * B; idx += NTHR) {
        int r = idx >> 7, c = idx & 127;
        sD[r * 129 + c] = g_A[base + (size_t)r * N + c];
    }
    __syncthreads();

    int tr = tid & 31, tj2 = tid >> 5;   // 32 x 16 lanes
    for (int c = 0; c < B - 1; c++) {
        float ipiv = __fdividef(1.f, sD[c * 129 + c]);
        for (int r = c + 1 + tr; r < B; r += 32) {
            float a = sD[r * 129 + c] * ipiv;
            for (int jj = c + 1 + tj2; jj <= r; jj += 16)
                sD[r * 129 + jj] -= a * sD[jj * 129 + c];
        }
        __syncthreads();
    }
    for (int c = tid; c < B; c += NTHR) invd[c] = rsqrtf(sD[c * 129 + c]);
    __syncthreads();
    for (int idx = tid; idx < B * B; idx += NTHR) {
        int r = idx >> 7, c = idx & 127;
        if (c < r) sD[r * 129 + c] *= invd[c];
        else if (c == r) sD[r * 129 + c] = invd[c];
    }
    __syncthreads();

    for (int r = 1; r < B; r++) {
        for (int c = tid; c < r; c += NTHR) rowbuf[c] = sD[r * 129 + c];
        __syncthreads();
        if (tid < r) {
            int c = tid;
            float a0 = 0.f, a1 = 0.f, a2 = 0.f, a3 = 0.f;
            int jj = c;
            for (; jj + 3 < r; jj += 4) {
                a0 += rowbuf[jj]     * sD[jj * 129 + c];
                a1 += rowbuf[jj + 1] * sD[(jj + 1) * 129 + c];
                a2 += rowbuf[jj + 2] * sD[(jj + 2) * 129 + c];
                a3 += rowbuf[jj + 3] * sD[(jj + 3) * 129 + c];
            }
            for (; jj < r; jj++) a0 += rowbuf[jj] * sD[jj * 129 + c];
            sD[r * 129 + c] = -invd[r] * ((a0 + a1) + (a2 + a3));
        }
        __syncthreads();
    }
    size_t koff = (size_t)kb * B * B;
    for (int idx = tid; idx < B * B; idx += NTHR) {
        int r = idx >> 7, c = idx & 127;
        float w = (c <= r) ? sD[r * 129 + c] : 0.f;
        g_invL[koff + idx] = w;
        __nv_bfloat16 h0, h1, h2;
        split3(w, h0, h1, h2);
        g_W0[koff + idx] = h0;
        g_W1[koff + idx] = h1;
        g_W2[koff + idx] = h2;
    }
    __syncthreads();
}

// ---------------- persistent right-looking cholesky (HMMA GEMMs) ----------------
__device__ __forceinline__ void barrier_phase(int pid) {
    __syncthreads();
    if (threadIdx.x == 0) {
        __threadfence();
        atomicAdd(&g_done[pid], 1);
        while (((volatile int*)g_done)[pid] < GRID_CHOL) __nanosleep(64);
        __threadfence();
    }
    __syncthreads();
}

__global__ void __launch_bounds__(NTHR, 1) chol_kernel() {
    extern __shared__ char dsm[];
    uint32_t sbase = s2u(dsm);
    __shared__ float invd[128];
    __shared__ float rowbuf[128];
    __shared__ int s_t;

    int tid = threadIdx.x;

    if (blockIdx.x == 0) potf_block(0, (float*)dsm, invd, rowbuf);
    barrier_phase(NB);

    for (int k = 0; k < NB - 1; k++) {
        int nb = NB - 1 - k;
        int ntask = nb + nb * (nb + 1) / 2;
        volatile int* tf = (volatile int*)(g_tflag + k * NB);
        size_t koff = (size_t)k * B * B;

        while (true) {
            if (tid == 0) s_t = atomicAdd(&g_cnt[k], 1);
            __syncthreads();
            int t = s_t;
            if (t >= ntask) break;

            if (t < nb) {
                int i = k + 1 + t;
                size_t poff = (size_t)(i * B) * N + (size_t)k * B;
                mma_tile(g_A + poff, 0, 0, 0, 0,
                         g_W0 + koff, g_W1 + koff, g_W2 + koff, B,
                         g_A + poff,
                         g_L0 + poff, g_L1 + poff, g_L2 + poff,
                         false, dsm, sbase);
                __threadfence();
                __syncthreads();
                if (tid == 0) atomicExch(&g_tflag[k * NB + i], 1);
            } else {
                int p, q;
                tri_decode_row(t - nb, p, q);
                int a = k + 1 + p, b = k + 1 + q;
                if (tid == 0) {
                    while (tf[a] == 0) __nanosleep(32);
                    while (tf[b] == 0) __nanosleep(32);
                }
                __syncthreads();
                __threadfence();
                size_t aoff = (size_t)(a * B) * N + (size_t)k * B;
                size_t boff = (size_t)(b * B) * N + (size_t)k * B;
                mma_tile(0, g_L0 + aoff, g_L1 + aoff, g_L2 + aoff, N,
                         g_L0 + boff, g_L1 + boff, g_L2 + boff, N,
                         g_A + (size_t)(a * B) * N + (size_t)b * B,
                         0, 0, 0, true, dsm, sbase);
                if (t == nb) {
                    __syncthreads();
                    potf_block(k + 1, (float*)dsm, invd, rowbuf);
                }
            }
            __syncthreads();
        }
        barrier_phase(k);
    }
}

// ---------------- spin-chained forward solve (512 thr) ----------------
__global__ void __launch_bounds__(512, 1) fwd_solve() {
    int k = blockIdx.x;
    int tid = threadIdx.x;
    int t = tid & 127, q = tid >> 7;
    __shared__ float svec[128];
    __shared__ float red[512];
    float acc = (q == 0) ? g_r[k * B + t] : 0.f;
    for (int j = 0; j < k; j++) {
        if (tid == 0) { while (((volatile int*)g_ff)[j] == 0) __nanosleep(32); }
        __syncthreads();
        __threadfence();
        if (tid < 128) svec[tid] = g_zsol[j * B + tid];
        __syncthreads();
        const float* Lr = g_A + (size_t)(k * B + t) * N + (size_t)j * B + q * 32;
        float a0 = 0.f, a1 = 0.f;
#pragma unroll
        for (int c = 0; c < 32; c += 8) {
            float4 l0 = *(const float4*)(Lr + c);
            float4 l1 = *(const float4*)(Lr + c + 4);
            int cc = q * 32 + c;
            a0 += l0.x * svec[cc] + l0.y * svec[cc + 1] + l0.z * svec[cc + 2] + l0.w * svec[cc + 3];
            a1 += l1.x * svec[cc + 4] + l1.y * svec[cc + 5] + l1.z * svec[cc + 6] + l1.w * svec[cc + 7];
        }
        acc -= a0 + a1;
        __syncthreads();
    }
    red[q * 128 + t] = acc;
    __syncthreads();
    if (tid < 128) svec[tid] = red[tid] + red[128 + tid] + red[256 + tid] + red[384 + tid];
    __syncthreads();
    const float* Wr = g_invL + (size_t)k * B * B + (size_t)t * B + q * 32;
    float z = 0.f;
#pragma unroll
    for (int c = 0; c < 32; c += 4) {
        float4 w = *(const float4*)(Wr + c);
        int cc = q * 32 + c;
        z += w.x * svec[cc] + w.y * svec[cc + 1] + w.z * svec[cc + 2] + w.w * svec[cc + 3];
    }
    red[q * 128 + t] = z;
    __syncthreads();
    if (tid < 128) g_zsol[k * B + tid] = red[tid] + red[128 + tid] + red[256 + tid] + red[384 + tid];
    __threadfence();
    __syncthreads();
    if (tid == 0) atomicExch(&g_ff[k], 1);
}

// ---------------- spin-chained backward solve (512 thr) ----------------
__global__ void __launch_bounds__(512, 1) bwd_solve() {
    int k = NB - 1 - blockIdx.x;
    int tid = threadIdx.x;
    int t = tid & 127, q = tid >> 7;
    __shared__ float svec[128];
    __shared__ float red[512];
    float acc = (q == 0) ? g_zsol[k * B + t] : 0.f;
    for (int j = k + 1; j < NB; j++) {
        if (tid == 0) { while (((volatile int*)g_fb)[j] == 0) __nanosleep(32); }
        __syncthreads();
        __threadfence();
        if (tid < 128) svec[tid] = g_alpha[j * B + tid];
        __syncthreads();
        const float* Lc = g_A + (size_t)(j * B + q * 32) * N + (size_t)k * B + t;
        float a0 = 0.f, a1 = 0.f, a2 = 0.f, a3 = 0.f;
#pragma unroll
        for (int r = 0; r < 32; r += 4) {
            int rr = q * 32 + r;
            a0 += Lc[(size_t)(r + 0) * N] * svec[rr + 0];
            a1 += Lc[(size_t)(r + 1) * N] * svec[rr + 1];
            a2 += Lc[(size_t)(r + 2) * N] * svec[rr + 2];
            a3 += Lc[(size_t)(r + 3) * N] * svec[rr + 3];
        }
        acc -= ((a0 + a1) + (a2 + a3));
        __syncthreads();
    }
    red[q * 128 + t] = acc;
    __syncthreads();
    if (tid < 128) svec[tid] = red[tid] + red[128 + tid] + red[256 + tid] + red[384 + tid];
    __syncthreads();
    const float* Wc = g_invL + (size_t)k * B * B + (size_t)(q * 32) * B + t;
    float al = 0.f;
#pragma unroll 8
    for (int r = 0; r < 32; r++) al += Wc[(size_t)r * B] * svec[q * 32 + r];
    red[q * 128 + t] = al;
    __syncthreads();
    if (tid < 128) g_alpha[k * B + tid] = red[tid] + red[128 + tid] + red[256 + tid] + red[384 + tid];
    __threadfence();
    __syncthreads();
    if (tid == 0) atomicExch(&g_fb[k], 1);
}

// ---------------- fused predict ----------------
__global__ void __launch_bounds__(256, 2) predict_kernel(const float* __restrict__ Xte,
                                                         const float* __restrict__ Xtr,
                                                         float* __restrict__ out) {
    __shared__ float sTr[32 * 132];
    __shared__ float sAl[128], sXX[128];
    __shared__ float sRed[256];
    int tid = threadIdx.x;
    int rl = tid >> 3, sl = tid & 7;
    int grow = blockIdx.x * 32 + rl;

    float xt[32];
#pragma unroll
    for (int dg = 0; dg < 8; dg++)
        *(float4*)(xt + dg * 4) = *(const float4*)(Xte + (size_t)grow * D + dg * 4);
    float xxt = 0.f;
#pragma unroll
    for (int d = 0; d < 32; d++) xxt += xt[d] * xt[d];

    float acc = 0.f;
    for (int ch = 0; ch < N / 128; ch++) {
        int pbase = ch * 128;
        __syncthreads();
#pragma unroll
        for (int i = 0; i < 4; i++) {
            int f = tid + i * 256;
            int p = f >> 3;
            int dg = (f & 7) << 2;
            float4 v = *(const float4*)(Xtr + (size_t)(pbase + p) * D + dg);
            sTr[(dg + 0) * 132 + p] = v.x; sTr[(dg + 1) * 132 + p] = v.y;
            sTr[(dg + 2) * 132 + p] = v.z; sTr[(dg + 3) * 132 + p] = v.w;
        }
        if (tid < 128) { sAl[tid] = g_alpha[pbase + tid]; sXX[tid] = g_xx[pbase + tid]; }
        __syncthreads();
#pragma unroll 4
        for (int i = 0; i < 16; i++) {
            int p = i * 8 + sl;
            float dot = 0.f;
#pragma unroll
            for (int d = 0; d < 32; d++) dot += xt[d] * sTr[d * 132 + p];
            float sq = fmaxf(xxt + sXX[p] - 2.f * dot, 0.f);
            acc += __expf(-GAMMA * sq) * sAl[p];
        }
    }
    sRed[rl * 8 + sl] = acc;
    __syncthreads();
    if (tid < 32) {
        float s = 0.f;
#pragma unroll
        for (int j = 0; j < 8; j++) s += sRed[tid * 8 + j];
        out[blockIdx.x * 32 + tid] = s;
    }
}

// ---------------- launcher ----------------
extern "C" void kernel_launch(void* const* d_in, const int* in_sizes, int n_in,
                              void* d_out, int out_size) {
    const float* Xtr = (const float*)d_in[0];
    const float* y   = (const float*)d_in[1];
    const float* Xte = (const float*)d_in[2];
    float* out = (float*)d_out;

    cudaFuncSetAttribute(chol_kernel, cudaFuncAttributeMaxDynamicSharedMemorySize, CHOL_DYN);

    prep_kernel<<<N / 256, 256>>>(Xtr, y);
    build_kernel<<<NB * (NB + 1) / 2, 256>>>(Xtr);
    noop_kernel<<<1, 1>>>();
    chol_kernel<<<GRID_CHOL, NTHR, CHOL_DYN>>>();   // 4th launch -> ncu captures this
    fwd_solve<<<NB, 512>>>();
    bwd_solve<<<NB, 512>>>();
    predict_kernel<<<N / 32, 256>>>(Xte, Xtr, out);
}

// round 12
// speedup vs baseline: 1.1500x; 1.0519x over previous
#include <cuda_runtime.h>
#include <cuda_fp16.h>
#include <math.h>
#include <stdint.h>

#define N 8192
#define D 32
#define NB 64
#define B 128
#define GAMMA 0.03125f
#define REG 1e-3f
#define GRID_CHOL 148
#define NTHR 512
#define SSTR 10240u          // one split buffer: 128 rows x 80B pitch
#define SB_OFF (2u * SSTR)   // B splits start (within a stage)
#define STGO (4u * SSTR)     // stage stride
#define CHOL_DYN (2 * 4 * 10240)   // 81920: 2 stages; also covers potf (66048) + epilogue (67584)

// ---------------- device scratch (zero-initialized at module load) ----------------
__device__ float g_A[(size_t)N * N];
__device__ float g_invL[(size_t)NB * B * B];
__device__ __align__(16) __half g_L0[(size_t)N * N];
__device__ __align__(16) __half g_L1[(size_t)N * N];
__device__ __align__(16) __half g_W0[(size_t)NB * B * B];
__device__ __align__(16) __half g_W1[(size_t)NB * B * B];
__device__ float g_xx[N];
__device__ float g_r[N];
__device__ float g_zsol[N];
__device__ float g_alpha[N];
// epoch-accumulating sync state (never reset)
__device__ int g_tflag[NB * NB];
__device__ int g_cnt[NB];
__device__ int g_done[NB + 1];
__device__ int g_ecnt;
__device__ int g_ff[NB];
__device__ int g_fb[NB];
__device__ int g_fep;
__device__ int g_bep;

// ---------------- helpers ----------------
__device__ __forceinline__ uint32_t s2u(const void* p) {
    uint32_t a;
    asm("{ .reg .u64 t; cvta.to.shared.u64 t, %1; cvt.u32.u64 %0, t; }" : "=r"(a) : "l"(p));
    return a;
}
__device__ __forceinline__ void ldsm_x4(uint32_t* d, uint32_t addr) {
    asm volatile("ldmatrix.sync.aligned.m8n8.x4.shared.b16 {%0,%1,%2,%3}, [%4];"
        : "=r"(d[0]), "=r"(d[1]), "=r"(d[2]), "=r"(d[3]) : "r"(addr));
}
__device__ __forceinline__ void ldsm_x2(uint32_t* d, uint32_t addr) {
    asm volatile("ldmatrix.sync.aligned.m8n8.x2.shared.b16 {%0,%1}, [%2];"
        : "=r"(d[0]), "=r"(d[1]) : "r"(addr));
}
__device__ __forceinline__ void mma16816(float* c, const uint32_t* a, const uint32_t* b) {
    asm volatile("mma.sync.aligned.m16n8k16.row.col.f32.f16.f16.f32 "
        "{%0,%1,%2,%3}, {%4,%5,%6,%7}, {%8,%9}, {%0,%1,%2,%3};"
        : "+f"(c[0]), "+f"(c[1]), "+f"(c[2]), "+f"(c[3])
        : "r"(a[0]), "r"(a[1]), "r"(a[2]), "r"(a[3]), "r"(b[0]), "r"(b[1]));
}
__device__ __forceinline__ void cpasync16(uint32_t saddr, const void* g) {
    asm volatile("cp.async.cg.shared.global [%0], [%1], 16;" :: "r"(saddr), "l"(g));
}
__device__ __forceinline__ void split2(float x, __half& h0, __half& h1) {
    h0 = __float2half_rn(x);
    h1 = __float2half_rn(x - __half2float(h0));
}
__device__ __forceinline__ void tri_decode_row(int p, int& ti, int& tj) {
    float pf = sqrtf(8.f * (float)p + 1.f);
    int i = (int)((pf - 1.f) * 0.5f);
    while ((i + 1) * (i + 2) / 2 <= p) i++;
    while (i * (i + 1) / 2 > p) i--;
    ti = i; tj = p - i * (i + 1) / 2;
}

__global__ void noop_kernel() {}

// ---------------- prep (no flag resets: epoch scheme accumulates) ----------------
__global__ void prep_kernel(const float* __restrict__ Xtr, const float* __restrict__ y) {
    int i = blockIdx.x * 256 + threadIdx.x;
    float s = 0.f;
#pragma unroll
    for (int dg = 0; dg < 8; dg++) {
        float4 v = *(const float4*)(Xtr + (size_t)i * D + dg * 4);
        s += v.x * v.x + v.y * v.y + v.z * v.z + v.w * v.w;
    }
    g_xx[i] = s;
    g_r[i] = y[i];
}

// ---------------- build gram (lower triangle of 128-blocks) ----------------
__global__ void __launch_bounds__(256, 2) build_kernel(const float* __restrict__ Xtr) {
    __shared__ float sXi[32 * 132];
    __shared__ float sXj[32 * 132];
    __shared__ float sxxi[128], sxxj[128];
    int tid = threadIdx.x;
    int bi, bj;
    tri_decode_row(blockIdx.x, bi, bj);

#pragma unroll
    for (int i = 0; i < 4; i++) {
        int f = tid + i * 256;
        int r = f >> 3;
        int dg = (f & 7) << 2;
        float4 v = *(const float4*)(Xtr + (size_t)(bi * B + r) * D + dg);
        sXi[(dg + 0) * 132 + r] = v.x; sXi[(dg + 1) * 132 + r] = v.y;
        sXi[(dg + 2) * 132 + r] = v.z; sXi[(dg + 3) * 132 + r] = v.w;
        float4 w = *(const float4*)(Xtr + (size_t)(bj * B + r) * D + dg);
        sXj[(dg + 0) * 132 + r] = w.x; sXj[(dg + 1) * 132 + r] = w.y;
        sXj[(dg + 2) * 132 + r] = w.z; sXj[(dg + 3) * 132 + r] = w.w;
    }
    if (tid < 128) { sxxi[tid] = g_xx[bi * B + tid]; sxxj[tid] = g_xx[bj * B + tid]; }
    __syncthreads();

    int tm = tid >> 4, tn = tid & 15;
    float acc[8][8];
#pragma unroll
    for (int i = 0; i < 8; i++)
#pragma unroll
        for (int j = 0; j < 8; j++) acc[i][j] = 0.f;

#pragma unroll
    for (int d = 0; d < 32; d++) {
        float a[8], b[8];
        *(float4*)(a)     = *(const float4*)(&sXi[d * 132 + tm * 8]);
        *(float4*)(a + 4) = *(const float4*)(&sXi[d * 132 + tm * 8 + 4]);
        *(float4*)(b)     = *(const float4*)(&sXj[d * 132 + tn * 8]);
        *(float4*)(b + 4) = *(const float4*)(&sXj[d * 132 + tn * 8 + 4]);
#pragma unroll
        for (int i = 0; i < 8; i++)
#pragma unroll
            for (int j = 0; j < 8; j++) acc[i][j] += a[i] * b[j];
    }

#pragma unroll
    for (int i = 0; i < 8; i++) {
        int li = tm * 8 + i;
        int gi = bi * B + li;
        float v[8];
#pragma unroll
        for (int j = 0; j < 8; j++) {
            int lj = tn * 8 + j;
            int gj = bj * B + lj;
            float sq = sxxi[li] + sxxj[lj] - 2.f * acc[i][j];
            sq = fmaxf(sq, 0.f);
            float val = __expf(-GAMMA * sq);
            if (gi == gj) val += REG;
            v[j] = val;
        }
        float* cp = g_A + (size_t)gi * N + bj * B + tn * 8;
        *(float4*)(cp)     = make_float4(v[0], v[1], v[2], v[3]);
        *(float4*)(cp + 4) = make_float4(v[4], v[5], v[6], v[7]);
    }
}

// ---------------- async stage: one operand (2 splits) of a 32-col chunk (512 thr) ----------------
__device__ __forceinline__ void stage_async2(const __half* p0, const __half* p1,
                                             int ld, int kk, uint32_t dst, int tid) {
#pragma unroll
    for (int i = 0; i < 2; i++) {
        int f = tid + (i << 9);
        int s = f >> 9;
        int rem = f & 511;
        int r = rem >> 2;
        int seg = rem & 3;
        const __half* p = s ? p1 : p0;
        cpasync16(dst + (uint32_t)s * SSTR + r * 80 + seg * 16,
                  p + (size_t)r * ld + kk + seg * 8);
    }
}

// ---------------- compute one 32-col chunk into acc (fp16x2, 3 products) ----------------
__device__ __forceinline__ void compute_chunk(uint32_t abase, uint32_t bbase,
                                              int lane, int wm, int wn,
                                              float acc[2][4][4]) {
#pragma unroll
    for (int kt = 0; kt < 2; kt++) {
#pragma unroll
        for (int sb = 0; sb < 2; sb++) {
            uint32_t bfr[4][2];
#pragma unroll
            for (int nt = 0; nt < 4; nt++) {
                int n = wn * 32 + nt * 8 + (lane & 7);
                int col = kt * 16 + ((lane >> 3) & 1) * 8;
                ldsm_x2(bfr[nt], bbase + (uint32_t)sb * SSTR + n * 80 + col * 2);
            }
#pragma unroll
            for (int sa = 0; sa < 2; sa++) {
                if (sa + sb > 1) continue;   // products: (0,0),(0,1),(1,0)
                uint32_t af[2][4];
#pragma unroll
                for (int mt = 0; mt < 2; mt++) {
                    int rrow = wm * 32 + mt * 16 + (lane & 15);
                    int col = kt * 16 + (lane >> 4) * 8;
                    ldsm_x4(af[mt], abase + (uint32_t)sa * SSTR + rrow * 80 + col * 2);
                }
#pragma unroll
                for (int mt = 0; mt < 2; mt++)
#pragma unroll
                    for (int nt = 0; nt < 4; nt++)
                        mma16816(acc[mt][nt], af[mt], bfr[nt]);
            }
        }
    }
}

// ---------------- HMMA fp16x2 tile GEMM: C (op)= A(128x128) * B(128x128)^T ----------------
__device__ void mma_tile(const float* Afp,
                         const __half* Ab0, const __half* Ab1, int lda,
                         const __half* Bb0, const __half* Bb1, int ldb,
                         float* C, __half* O0, __half* O1,
                         bool sub, char* dsm, uint32_t sbase) {
    int tid = threadIdx.x;
    int lane = tid & 31, warp = tid >> 5;
    int wm = warp & 3, wn = warp >> 2;

    float acc[2][4][4];
#pragma unroll
    for (int mt = 0; mt < 2; mt++)
#pragma unroll
        for (int nt = 0; nt < 4; nt++)
#pragma unroll
            for (int e = 0; e < 4; e++) acc[mt][nt][e] = 0.f;

    if (Afp) {
        // ---- trsm path: single stage, A split synchronously ----
        for (int ck = 0; ck < 4; ck++) {
            int kk = ck * 32;
            stage_async2(Bb0, Bb1, ldb, kk, sbase + SB_OFF, tid);
            asm volatile("cp.async.commit_group;");
#pragma unroll
            for (int i = 0; i < 8; i++) {
                int f = tid + (i << 9);
                int r = f >> 5, c = f & 31;
                float v = Afp[(size_t)r * N + kk + c];
                __half h0, h1;
                split2(v, h0, h1);
                int so = r * 80 + c * 2;
                *(__half*)(dsm + so) = h0;
                *(__half*)(dsm + SSTR + so) = h1;
            }
            asm volatile("cp.async.wait_group 0;" ::: "memory");
            __syncthreads();
            compute_chunk(sbase, sbase + SB_OFF, lane, wm, wn, acc);
            __syncthreads();
        }
    } else {
        // ---- syrk path: 2-stage cp.async pipeline ----
        stage_async2(Ab0, Ab1, lda, 0, sbase, tid);
        stage_async2(Bb0, Bb1, ldb, 0, sbase + SB_OFF, tid);
        asm volatile("cp.async.commit_group;");
#pragma unroll
        for (int ck = 0; ck < 4; ck++) {
            uint32_t cur = sbase + (uint32_t)(ck & 1) * STGO;
            if (ck < 3) {
                uint32_t nxt = sbase + (uint32_t)((ck + 1) & 1) * STGO;
                int kk = (ck + 1) * 32;
                stage_async2(Ab0, Ab1, lda, kk, nxt, tid);
                stage_async2(Bb0, Bb1, ldb, kk, nxt + SB_OFF, tid);
                asm volatile("cp.async.commit_group;");
                asm volatile("cp.async.wait_group 1;" ::: "memory");
            } else {
                asm volatile("cp.async.wait_group 0;" ::: "memory");
            }
            __syncthreads();
            compute_chunk(cur, cur + SB_OFF, lane, wm, wn, acc);
            __syncthreads();
        }
    }

    // epilogue via smem staging (two 64-row halves), coalesced fp32 update
    float* sE = (float*)dsm;
    for (int half = 0; half < 2; half++) {
        if ((wm >> 1) == half) {
#pragma unroll
            for (int mt = 0; mt < 2; mt++)
#pragma unroll
                for (int nt = 0; nt < 4; nt++) {
                    int rb = (wm & 1) * 32 + mt * 16 + (lane >> 2);
                    int cb = wn * 32 + nt * 8 + (lane & 3) * 2;
                    sE[rb * 132 + cb]           = acc[mt][nt][0];
                    sE[rb * 132 + cb + 1]       = acc[mt][nt][1];
                    sE[(rb + 8) * 132 + cb]     = acc[mt][nt][2];
                    sE[(rb + 8) * 132 + cb + 1] = acc[mt][nt][3];
                }
        }
        __syncthreads();
#pragma unroll
        for (int i = 0; i < 4; i++) {
            int flat = i * NTHR + tid;
            int rr = flat >> 5;
            int c4 = (flat & 31) * 4;
            int grow = half * 64 + rr;
            float* cp = C + (size_t)grow * N + c4;
            float4 s = *(float4*)(sE + rr * 132 + c4);
            if (sub) {
                float4 c0 = *(float4*)cp;
                c0.x -= s.x; c0.y -= s.y; c0.z -= s.z; c0.w -= s.w;
                *(float4*)cp = c0;
            } else {
                *(float4*)cp = s;
                size_t ob = (size_t)grow * N + c4;
                __half a0, a1, b0, b1, c0_, c1_, d0, d1;
                split2(s.x, a0, a1); split2(s.y, b0, b1);
                split2(s.z, c0_, c1_); split2(s.w, d0, d1);
                *(__half2*)(O0 + ob)     = __halves2half2(a0, b0);
                *(__half2*)(O0 + ob + 2) = __halves2half2(c0_, d0);
                *(__half2*)(O1 + ob)     = __halves2half2(a1, b1);
                *(__half2*)(O1 + ob + 2) = __halves2half2(c1_, d1);
            }
        }
        __syncthreads();
    }
}

// ---------------- potf: factor diag block kb, write invL + fp16 splits (512 thr) ----------------
__device__ void potf_block(int kb, float* sD, float* invd, float* rowbuf) {
    int tid = threadIdx.x;
    size_t base = (size_t)(kb * B) * N + (size_t)kb * B;

    for (int idx = tid; idx < B * B; idx += NTHR) {
        int r = idx >> 7, c = idx & 127;
        sD[r * 129 + c] = g_A[base + (size_t)r * N + c];
    }
    __syncthreads();

    int tr = tid & 31, tj2 = tid >> 5;
    for (int c = 0; c < B - 1; c++) {
        float ipiv = __fdividef(1.f, sD[c * 129 + c]);
        for (int r = c + 1 + tr; r < B; r += 32) {
            float a = sD[r * 129 + c] * ipiv;
            for (int jj = c + 1 + tj2; jj <= r; jj += 16)
                sD[r * 129 + jj] -= a * sD[jj * 129 + c];
        }
        __syncthreads();
    }
    for (int c = tid; c < B; c += NTHR) invd[c] = rsqrtf(sD[c * 129 + c]);
    __syncthreads();
    for (int idx = tid; idx < B * B; idx += NTHR) {
        int r = idx >> 7, c = idx & 127;
        if (c < r) sD[r * 129 + c] *= invd[c];
        else if (c == r) sD[r * 129 + c] = invd[c];
    }
    __syncthreads();

    for (int r = 1; r < B; r++) {
        for (int c = tid; c < r; c += NTHR) rowbuf[c] = sD[r * 129 + c];
        __syncthreads();
        if (tid < r) {
            int c = tid;
            float a0 = 0.f, a1 = 0.f, a2 = 0.f, a3 = 0.f;
            int jj = c;
            for (; jj + 3 < r; jj += 4) {
                a0 += rowbuf[jj]     * sD[jj * 129 + c];
                a1 += rowbuf[jj + 1] * sD[(jj + 1) * 129 + c];
                a2 += rowbuf[jj + 2] * sD[(jj + 2) * 129 + c];
                a3 += rowbuf[jj + 3] * sD[(jj + 3) * 129 + c];
            }
            for (; jj < r; jj++) a0 += rowbuf[jj] * sD[jj * 129 + c];
            sD[r * 129 + c] = -invd[r] * ((a0 + a1) + (a2 + a3));
        }
        __syncthreads();
    }
    size_t koff = (size_t)kb * B * B;
    for (int idx = tid; idx < B * B; idx += NTHR) {
        int r = idx >> 7, c = idx & 127;
        float w = (c <= r) ? sD[r * 129 + c] : 0.f;
        g_invL[koff + idx] = w;
        __half h0, h1;
        split2(w, h0, h1);
        g_W0[koff + idx] = h0;
        g_W1[koff + idx] = h1;
    }
    __syncthreads();
}

// ---------------- persistent right-looking cholesky (epoch-safe) ----------------
__device__ __forceinline__ void barrier_phase(int pid, int epoch) {
    __syncthreads();
    if (threadIdx.x == 0) {
        __threadfence();
        atomicAdd(&g_done[pid], 1);
        while (((volatile int*)g_done)[pid] < epoch * GRID_CHOL) __nanosleep(64);
        __threadfence();
    }
    __syncthreads();
}

__global__ void __launch_bounds__(NTHR, 1) chol_kernel() {
    extern __shared__ char dsm[];
    uint32_t sbase = s2u(dsm);
    __shared__ float invd[128];
    __shared__ float rowbuf[128];
    __shared__ int s_t;
    __shared__ int s_e;

    int tid = threadIdx.x;
    if (tid == 0) s_e = atomicAdd(&g_ecnt, 1) / GRID_CHOL + 1;
    __syncthreads();
    int epoch = s_e;

    if (blockIdx.x == 0) potf_block(0, (float*)dsm, invd, rowbuf);
    barrier_phase(NB, epoch);

    for (int k = 0; k < NB - 1; k++) {
        int nb = NB - 1 - k;
        int ntask = nb + nb * (nb + 1) / 2;
        int base = (epoch - 1) * (ntask + GRID_CHOL);
        volatile int* tf = (volatile int*)(g_tflag + k * NB);
        size_t koff = (size_t)k * B * B;

        while (true) {
            if (tid == 0) s_t = atomicAdd(&g_cnt[k], 1) - base;
            __syncthreads();
            int t = s_t;
            if (t >= ntask) break;

            if (t < nb) {
                int i = k + 1 + t;
                size_t poff = (size_t)(i * B) * N + (size_t)k * B;
                mma_tile(g_A + poff, 0, 0, 0,
                         g_W0 + koff, g_W1 + koff, B,
                         g_A + poff, g_L0 + poff, g_L1 + poff,
                         false, dsm, sbase);
                __threadfence();
                __syncthreads();
                if (tid == 0) atomicAdd(&g_tflag[k * NB + i], 1);
            } else {
                int p, q;
                tri_decode_row(t - nb, p, q);
                int a = k + 1 + p, b = k + 1 + q;
                if (tid == 0) {
                    while (tf[a] < epoch) __nanosleep(32);
                    while (tf[b] < epoch) __nanosleep(32);
                }
                __syncthreads();
                __threadfence();
                size_t aoff = (size_t)(a * B) * N + (size_t)k * B;
                size_t boff = (size_t)(b * B) * N + (size_t)k * B;
                mma_tile(0, g_L0 + aoff, g_L1 + aoff, N,
                         g_L0 + boff, g_L1 + boff, N,
                         g_A + (size_t)(a * B) * N + (size_t)b * B, 0, 0,
                         true, dsm, sbase);
                if (t == nb) {
                    __syncthreads();
                    potf_block(k + 1, (float*)dsm, invd, rowbuf);
                }
            }
            __syncthreads();
        }
        barrier_phase(k, epoch);
    }
}

// ---------------- spin-chained forward solve (epoch-safe) ----------------
__global__ void __launch_bounds__(512, 1) fwd_solve() {
    int k = blockIdx.x;
    int tid = threadIdx.x;
    int t = tid & 127, q = tid >> 7;
    __shared__ float svec[128];
    __shared__ float red[512];
    __shared__ int s_e;
    if (tid == 0) s_e = atomicAdd(&g_fep, 1) / NB + 1;
    __syncthreads();
    int e = s_e;
    float acc = (q == 0) ? g_r[k * B + t] : 0.f;
    for (int j = 0; j < k; j++) {
        if (tid == 0) { while (((volatile int*)g_ff)[j] < e) __nanosleep(32); }
        __syncthreads();
        __threadfence();
        if (tid < 128) svec[tid] = g_zsol[j * B + tid];
        __syncthreads();
        const float* Lr = g_A + (size_t)(k * B + t) * N + (size_t)j * B + q * 32;
        float a0 = 0.f, a1 = 0.f;
#pragma unroll
        for (int c = 0; c < 32; c += 8) {
            float4 l0 = *(const float4*)(Lr + c);
            float4 l1 = *(const float4*)(Lr + c + 4);
            int cc = q * 32 + c;
            a0 += l0.x * svec[cc] + l0.y * svec[cc + 1] + l0.z * svec[cc + 2] + l0.w * svec[cc + 3];
            a1 += l1.x * svec[cc + 4] + l1.y * svec[cc + 5] + l1.z * svec[cc + 6] + l1.w * svec[cc + 7];
        }
        acc -= a0 + a1;
        __syncthreads();
    }
    red[q * 128 + t] = acc;
    __syncthreads();
    if (tid < 128) svec[tid] = red[tid] + red[128 + tid] + red[256 + tid] + red[384 + tid];
    __syncthreads();
    const float* Wr = g_invL + (size_t)k * B * B + (size_t)t * B + q * 32;
    float z = 0.f;
#pragma unroll
    for (int c = 0; c < 32; c += 4) {
        float4 w = *(const float4*)(Wr + c);
        int cc = q * 32 + c;
        z += w.x * svec[cc] + w.y * svec[cc + 1] + w.z * svec[cc + 2] + w.w * svec[cc + 3];
    }
    red[q * 128 + t] = z;
    __syncthreads();
    if (tid < 128) g_zsol[k * B + tid] = red[tid] + red[128 + tid] + red[256 + tid] + red[384 + tid];
    __threadfence();
    __syncthreads();
    if (tid == 0) atomicAdd(&g_ff[k], 1);
}

// ---------------- spin-chained backward solve (epoch-safe) ----------------
__global__ void __launch_bounds__(512, 1) bwd_solve() {
    int k = NB - 1 - blockIdx.x;
    int tid = threadIdx.x;
    int t = tid & 127, q = tid >> 7;
    __shared__ float svec[128];
    __shared__ float red[512];
    __shared__ int s_e;
    if (tid == 0) s_e = atomicAdd(&g_bep, 1) / NB + 1;
    __syncthreads();
    int e = s_e;
    float acc = (q == 0) ? g_zsol[k * B + t] : 0.f;
    for (int j = k + 1; j < NB; j++) {
        if (tid == 0) { while (((volatile int*)g_fb)[j] < e) __nanosleep(32); }
        __syncthreads();
        __threadfence();
        if (tid < 128) svec[tid] = g_alpha[j * B + tid];
        __syncthreads();
        const float* Lc = g_A + (size_t)(j * B + q * 32) * N + (size_t)k * B + t;
        float a0 = 0.f, a1 = 0.f, a2 = 0.f, a3 = 0.f;
#pragma unroll
        for (int r = 0; r < 32; r += 4) {
            int rr = q * 32 + r;
            a0 += Lc[(size_t)(r + 0) * N] * svec[rr + 0];
            a1 += Lc[(size_t)(r + 1) * N] * svec[rr + 1];
            a2 += Lc[(size_t)(r + 2) * N] * svec[rr + 2];
            a3 += Lc[(size_t)(r + 3) * N] * svec[rr + 3];
        }
        acc -= ((a0 + a1) + (a2 + a3));
        __syncthreads();
    }
    red[q * 128 + t] = acc;
    __syncthreads();
    if (tid < 128) svec[tid] = red[tid] + red[128 + tid] + red[256 + tid] + red[384 + tid];
    __syncthreads();
    const float* Wc = g_invL + (size_t)k * B * B + (size_t)(q * 32) * B + t;
    float al = 0.f;
#pragma unroll 8
    for (int r = 0; r < 32; r++) al += Wc[(size_t)r * B] * svec[q * 32 + r];
    red[q * 128 + t] = al;
    __syncthreads();
    if (tid < 128) g_alpha[k * B + tid] = red[tid] + red[128 + tid] + red[256 + tid] + red[384 + tid];
    __threadfence();
    __syncthreads();
    if (tid == 0) atomicAdd(&g_fb[k], 1);
}

// ---------------- fused predict ----------------
__global__ void __launch_bounds__(256, 2) predict_kernel(const float* __restrict__ Xte,
                                                         const float* __restrict__ Xtr,
                                                         float* __restrict__ out) {
    __shared__ float sTr[32 * 132];
    __shared__ float sAl[128], sXX[128];
    __shared__ float sRed[256];
    int tid = threadIdx.x;
    int rl = tid >> 3, sl = tid & 7;
    int grow = blockIdx.x * 32 + rl;

    float xt[32];
#pragma unroll
    for (int dg = 0; dg < 8; dg++)
        *(float4*)(xt + dg * 4) = *(const float4*)(Xte + (size_t)grow * D + dg * 4);
    float xxt = 0.f;
#pragma unroll
    for (int d = 0; d < 32; d++) xxt += xt[d] * xt[d];

    float acc = 0.f;
    for (int ch = 0; ch < N / 128; ch++) {
        int pbase = ch * 128;
        __syncthreads();
#pragma unroll
        for (int i = 0; i < 4; i++) {
            int f = tid + i * 256;
            int p = f >> 3;
            int dg = (f & 7) << 2;
            float4 v = *(const float4*)(Xtr + (size_t)(pbase + p) * D + dg);
            sTr[(dg + 0) * 132 + p] = v.x; sTr[(dg + 1) * 132 + p] = v.y;
            sTr[(dg + 2) * 132 + p] = v.z; sTr[(dg + 3) * 132 + p] = v.w;
        }
        if (tid < 128) { sAl[tid] = g_alpha[pbase + tid]; sXX[tid] = g_xx[pbase + tid]; }
        __syncthreads();
#pragma unroll 4
        for (int i = 0; i < 16; i++) {
            int p = i * 8 + sl;
            float dot = 0.f;
#pragma unroll
            for (int d = 0; d < 32; d++) dot += xt[d] * sTr[d * 132 + p];
            float sq = fmaxf(xxt + sXX[p] - 2.f * dot, 0.f);
            acc += __expf(-GAMMA * sq) * sAl[p];
        }
    }
    sRed[rl * 8 + sl] = acc;
    __syncthreads();
    if (tid < 32) {
        float s = 0.f;
#pragma unroll
        for (int j = 0; j < 8; j++) s += sRed[tid * 8 + j];
        out[blockIdx.x * 32 + tid] = s;
    }
}

// ---------------- launcher ----------------
extern "C" void kernel_launch(void* const* d_in, const int* in_sizes, int n_in,
                              void* d_out, int out_size) {
    const float* Xtr = (const float*)d_in[0];
    const float* y   = (const float*)d_in[1];
    const float* Xte = (const float*)d_in[2];
    float* out = (float*)d_out;

    cudaFuncSetAttribute(chol_kernel, cudaFuncAttributeMaxDynamicSharedMemorySize, CHOL_DYN);

    prep_kernel<<<N / 256, 256>>>(Xtr, y);
    build_kernel<<<NB * (NB + 1) / 2, 256>>>(Xtr);
    noop_kernel<<<1, 1>>>();
    chol_kernel<<<GRID_CHOL, NTHR, CHOL_DYN>>>();   // 4th launch; now replay-safe for ncu
    fwd_solve<<<NB, 512>>>();
    bwd_solve<<<NB, 512>>>();
    predict_kernel<<<N / 32, 256>>>(Xte, Xtr, out);
}